// round 8
// baseline (speedup 1.0000x reference)
#include <cuda_runtime.h>
#include <math.h>
#include <stdint.h>

// ---------------- problem constants ----------------
#define BB   128
#define TT   1024
#define II   256
#define HH   512
#define OO   256
#define LOUT 64
#define NCTA 128          // 16 clusters x 8 CTAs

#define WOP  516          // W_out smem row stride (floats)
#define XS   130          // xproj smem row stride

#define XPROJ_SMEM (2 * 64 * XS * 4)
// k_rnn smem floats: hb 8192, part 4096, wouts 32*WOP=16512, sbhh 512, sbih 512,
// sbout 256, sort scratch 16 ints
#define RNN_FLOATS (8192 + 4096 + 32*WOP + 512 + 512 + 256 + 16)
#define RNN_SMEM   (RNN_FLOATS * 4)

__device__ float g_xproj[(size_t)BB * TT * HH];   // 256 MB scratch

union U64 { unsigned long long u; float2 f; };

__device__ __forceinline__ void ffma2(U64 &d, unsigned long long a, U64 b) {
    asm("fma.rn.f32x2 %0, %1, %2, %0;" : "+l"(d.u) : "l"(a), "l"(b.u));
}

__device__ __forceinline__ uint32_t smem_u32(const void* p) {
    return (uint32_t)__cvta_generic_to_shared(p);
}

#define CLUSTER_SYNC() do { \
    asm volatile("barrier.cluster.arrive.aligned;" ::: "memory"); \
    asm volatile("barrier.cluster.wait.aligned;"   ::: "memory"); \
} while (0)

// ============================================================================
// Kernel 1: x_proj = x @ W_ih^T + b_ih  (unchanged; proven)
// ============================================================================
__global__ void __launch_bounds__(256, 2)
k_xproj(const float* __restrict__ x, const int* __restrict__ lengths,
        const float* __restrict__ W_ih, const float* __restrict__ b_ih)
{
    extern __shared__ float sm[];
    float* xs = sm;
    float* ws = sm + 64 * XS;

    const int b  = blockIdx.z;
    const int t0 = blockIdx.y * 64;
    const int h0 = blockIdx.x * 64;
    if (t0 >= lengths[b]) return;

    const int tid = threadIdx.x;
    const int tr  = tid >> 4;
    const int tc  = tid & 15;

    U64 acc[4][4];
    #pragma unroll
    for (int i = 0; i < 4; i++)
        #pragma unroll
        for (int j = 0; j < 4; j++) acc[i][j].u = 0ULL;

    for (int kc = 0; kc < 2; kc++) {
        __syncthreads();
        #pragma unroll
        for (int i = 0; i < 16; i++) {
            int e = tid + 256 * i;
            int r = e >> 6, cc = e & 63;
            float2 xv = *(const float2*)(x + ((size_t)b * TT + t0 + r) * II + kc * 128 + 2 * cc);
            *(float2*)(xs + r * XS + 2 * cc) = xv;
            float2 wv = *(const float2*)(W_ih + (size_t)(h0 + r) * II + kc * 128 + 2 * cc);
            *(float2*)(ws + r * XS + 2 * cc) = wv;
        }
        __syncthreads();
        #pragma unroll 4
        for (int kp = 0; kp < 64; kp++) {
            U64 xf[4], wf[4];
            #pragma unroll
            for (int i = 0; i < 4; i++) xf[i].f = *(const float2*)(xs + (tr + 16*i) * XS + 2 * kp);
            #pragma unroll
            for (int j = 0; j < 4; j++) wf[j].f = *(const float2*)(ws + (tc + 16*j) * XS + 2 * kp);
            #pragma unroll
            for (int i = 0; i < 4; i++)
                #pragma unroll
                for (int j = 0; j < 4; j++) ffma2(acc[i][j], xf[i].u, wf[j]);
        }
    }

    #pragma unroll
    for (int i = 0; i < 4; i++)
        #pragma unroll
        for (int j = 0; j < 4; j++) {
            int t = t0 + tr + 16 * i;
            int h = h0 + tc + 16 * j;
            g_xproj[((size_t)b * TT + t) * HH + h] = acc[i][j].f.x + acc[i][j].f.y + b_ih[h];
        }
}

// ============================================================================
// Kernel 2: clustered persistent RNN with LENGTH-SORTED ROW COMPACTION.
// Rows stored in h-buffer by sorted slot (descending length). Active set at
// step t is the prefix nact(t) -> GEMM is a dynamic uniform loop; inactive
// rows issue ZERO instructions (vs predicated-out in R4-R6).
// ============================================================================
__global__ void __launch_bounds__(512, 1) __cluster_dims__(8, 1, 1)
k_rnn(const int* __restrict__ lengths, const float* __restrict__ W_hh,
      const float* __restrict__ b_hh, const float* __restrict__ b_ih,
      const float* __restrict__ W_out, const float* __restrict__ b_out,
      float* __restrict__ out)
{
    extern __shared__ float sm[];
    float* hb    = sm;                 // [2][8][512] double-buffered h, by sorted slot
    float* part  = sm + 8192;          // [8][512] k-split partials
    float* wouts = part + 4096;        // [32][WOP]
    float* sbhh  = wouts + 32 * WOP;   // [512]
    float* sbih  = sbhh + 512;         // [512]
    float* sbout = sbih + 512;         // [256]
    int*   s_ord = (int*)(sbout + 256);// [8] slot -> batch row (within cluster)
    int*   s_len = s_ord + 8;          // [8] sorted lengths (descending)

    const int tid    = threadIdx.x;
    const int cta    = blockIdx.x;
    const int rg     = cta >> 3;
    const int cg     = cta & 7;
    const int c      = tid & 63;
    const int kq     = tid >> 6;       // 0..7: k-chunk AND owned output slot
    const int b_base = rg * 8;
    const int col_c  = cg * 64 + c;

    // DSMEM peer bases for hb
    uint32_t peer[8];
    {
        uint32_t hbase = smem_u32(hb);
        #pragma unroll
        for (int rk = 0; rk < 8; rk++)
            asm("mapa.shared::cluster.u32 %0, %1, %2;" : "=r"(peer[rk]) : "r"(hbase), "r"(rk));
    }

    // W_hh[col_c][kq*64 .. +64] -> 32 U64 regs (permanent)
    U64 W[32];
    {
        const U64* wsrc = (const U64*)(W_hh + (size_t)col_c * HH + kq * 64);
        #pragma unroll
        for (int j = 0; j < 32; j++) W[j] = wsrc[j];
    }

    // stage biases + W_out slice; zero hb[0]
    sbhh[tid] = b_hh[tid]; sbih[tid] = b_ih[tid];
    if (tid < 256) sbout[tid] = b_out[tid];
    #pragma unroll
    for (int i = 0; i < 16; i++) {
        int e = tid + 512 * i;
        int r = e >> 8, cc = e & 255;
        float2 v = *(const float2*)(W_out + (size_t)(cg * 32 + r) * HH + 2 * cc);
        *(float2*)(wouts + r * WOP + 2 * cc) = v;
    }
    #pragma unroll
    for (int i = 0; i < 8; i++) hb[tid + 512 * i] = 0.f;   // hb[0] = 0

    // sort rows by descending length (stable). tid 0 writes slot tables.
    if (tid == 0) {
        int Lr[8];
        #pragma unroll
        for (int r = 0; r < 8; r++) Lr[r] = lengths[b_base + r];
        #pragma unroll
        for (int i = 0; i < 8; i++) {
            int rk = 0;
            #pragma unroll
            for (int j = 0; j < 8; j++)
                rk += (Lr[j] > Lr[i]) || (Lr[j] == Lr[i] && j < i);
            s_ord[rk] = i;
            s_len[rk] = Lr[i];
        }
    }
    __syncthreads();

    const float bhh_c = sbhh[col_c];
    const float bih_c = sbih[col_c];
    const int l0 = s_len[0], l1 = s_len[1], l2 = s_len[2], l3 = s_len[3],
              l4 = s_len[4], l5 = s_len[5], l6 = s_len[6], l7 = s_len[7];
    const int L_own   = s_len[kq];                 // my slot's length
    const int row_own = s_ord[kq];                 // my slot's batch row
    const int tmax    = l0;
    const float* xp_base = g_xproj + ((size_t)(b_base + row_own) * TT) * HH + col_c;

    CLUSTER_SYNC();        // hb[0] + tables visible cluster-wide before any push

    // =================== encoder (to this cluster's tmax) =====================
    float xp_next = (0 < L_own) ? xp_base[0] : 0.f;

    for (int t = 0; t < tmax; t++) {
        const int rp = t & 1, wp = rp ^ 1;

        const float xp = xp_next;
        if (t + 1 < L_own) xp_next = xp_base[(size_t)(t + 1) * HH];   // hide DRAM

        // active prefix count (rows sorted by descending length)
        const int na = (t < l0) + (t < l1) + (t < l2) + (t < l3)
                     + (t < l4) + (t < l5) + (t < l6) + (t < l7);

        // GEMM over ACTIVE slots only (uniform dynamic loop -> real skip)
        const float* hrow = hb + rp * 4096 + kq * 64;
        float* prow = part + kq * 512 + c;
        #pragma unroll 1
        for (int ri = 0; ri < na; ri++) {
            const ulonglong2* h2 = (const ulonglong2*)(hrow + ri * 512);
            U64 a0, a1, a2, a3;
            a0.u = a1.u = a2.u = a3.u = 0ULL;
            #pragma unroll
            for (int j = 0; j < 8; j++) {
                ulonglong2 q0 = h2[2 * j];
                ulonglong2 q1 = h2[2 * j + 1];
                ffma2(a0, q0.x, W[4 * j]);
                ffma2(a1, q0.y, W[4 * j + 1]);
                ffma2(a2, q1.x, W[4 * j + 2]);
                ffma2(a3, q1.y, W[4 * j + 3]);
            }
            prow[ri * 64] = ((a0.f.x + a1.f.x) + (a0.f.y + a1.f.y))
                          + ((a2.f.x + a3.f.x) + (a2.f.y + a3.f.y));
        }
        __syncthreads();

        // reduce + tanh + push to all 8 ranks (thread owns slot kq, col c)
        if (t < L_own) {
            float s = bhh_c + xp;
            #pragma unroll
            for (int k = 0; k < 8; k++) s += part[k * 512 + kq * 64 + c];
            float v = tanhf(s);
            uint32_t off = (uint32_t)(wp * 4096 + kq * 512 + col_c) * 4u;
            #pragma unroll
            for (int rk = 0; rk < 8; rk++)
                asm volatile("st.shared::cluster.f32 [%0], %1;"
                             :: "r"(peer[rk] + off), "f"(v) : "memory");
        }

        CLUSTER_SYNC();   // release pushes / acquire peers'; also syncs the CTA
    }

    // normalize: slots whose final value sits in buffer 1 -> buffer 0 (local)
    if (l0 & 1) hb[0 * 512 + tid] = hb[4096 + 0 * 512 + tid];
    if (l1 & 1) hb[1 * 512 + tid] = hb[4096 + 1 * 512 + tid];
    if (l2 & 1) hb[2 * 512 + tid] = hb[4096 + 2 * 512 + tid];
    if (l3 & 1) hb[3 * 512 + tid] = hb[4096 + 3 * 512 + tid];
    if (l4 & 1) hb[4 * 512 + tid] = hb[4096 + 4 * 512 + tid];
    if (l5 & 1) hb[5 * 512 + tid] = hb[4096 + 5 * 512 + tid];
    if (l6 & 1) hb[6 * 512 + tid] = hb[4096 + 6 * 512 + tid];
    if (l7 & 1) hb[7 * 512 + tid] = hb[4096 + 7 * 512 + tid];
    __syncthreads();
    CLUSTER_SYNC();       // no decoder push may land before normalize completes

    // =================== decoder (64 steps) ===================================
    for (int s = 0; s < LOUT; s++) {
        const int rp = s & 1, wp = rp ^ 1;

        #pragma unroll
        for (int ri = 0; ri < 8; ri++) {
            const ulonglong2* h2 = (const ulonglong2*)(hb + rp * 4096 + ri * 512 + kq * 64);
            U64 a0, a1, a2, a3;
            a0.u = a1.u = a2.u = a3.u = 0ULL;
            #pragma unroll
            for (int j = 0; j < 8; j++) {
                ulonglong2 q0 = h2[2 * j];
                ulonglong2 q1 = h2[2 * j + 1];
                ffma2(a0, q0.x, W[4 * j]);
                ffma2(a1, q0.y, W[4 * j + 1]);
                ffma2(a2, q1.x, W[4 * j + 2]);
                ffma2(a3, q1.y, W[4 * j + 3]);
            }
            part[kq * 512 + ri * 64 + c] = ((a0.f.x + a1.f.x) + (a0.f.y + a1.f.y))
                                         + ((a2.f.x + a3.f.x) + (a2.f.y + a3.f.y));
        }
        __syncthreads();

        {
            float sv = bih_c + bhh_c;
            #pragma unroll
            for (int k = 0; k < 8; k++) sv += part[k * 512 + kq * 64 + c];
            float v = tanhf(sv);
            uint32_t off = (uint32_t)(wp * 4096 + kq * 512 + col_c) * 4u;
            #pragma unroll
            for (int rk = 0; rk < 8; rk++)
                asm volatile("st.shared::cluster.f32 [%0], %1;"
                             :: "r"(peer[rk] + off), "f"(v) : "memory");
        }

        CLUSTER_SYNC();    // new h (parity wp) complete in every replica

        // out[b, s, cg*32+oo]; slot rr maps to batch row s_ord[rr]
        if (tid < 256) {
            const int rr = tid >> 5;
            const int oo = tid & 31;
            const ulonglong2* h2 = (const ulonglong2*)(hb + wp * 4096 + rr * 512);
            const ulonglong2* w2 = (const ulonglong2*)(wouts + oo * WOP);
            U64 a0, a1; a0.u = 0ULL; a1.u = 0ULL;
            #pragma unroll 8
            for (int j = 0; j < 128; j++) {
                ulonglong2 qh = h2[j];
                ulonglong2 qw = w2[j];
                U64 wb0, wb1; wb0.u = qw.x; wb1.u = qw.y;
                ffma2(a0, qh.x, wb0);
                ffma2(a1, qh.y, wb1);
            }
            float val = (a0.f.x + a1.f.x) + (a0.f.y + a1.f.y) + sbout[cg * 32 + oo];
            out[((size_t)(b_base + s_ord[rr]) * LOUT + s) * OO + cg * 32 + oo] = val;
        }
        // safe vs next step: pushes target parity rp (!= wp read here) and are
        // gated by the next CLUSTER_SYNC, which needs all threads' arrival.
    }

    CLUSTER_SYNC();   // keep cluster alive until all DSMEM traffic quiesces
}

// ---------------- launch ----------------
extern "C" void kernel_launch(void* const* d_in, const int* in_sizes, int n_in,
                              void* d_out, int out_size)
{
    int k = 0;
    const float* x       = (const float*)d_in[k++];
    const int*   lengths = (const int*)  d_in[k++];
    if (k < n_in && in_sizes[k] == 1) k++;           // out_lengths scalar (if present)
    const float* W_ih    = (const float*)d_in[k++];
    const float* b_ih    = (const float*)d_in[k++];
    const float* W_hh    = (const float*)d_in[k++];
    const float* b_hh    = (const float*)d_in[k++];
    const float* W_out   = (const float*)d_in[k++];
    const float* b_out   = (const float*)d_in[k++];
    float* out = (float*)d_out;

    cudaFuncSetAttribute(k_xproj, cudaFuncAttributeMaxDynamicSharedMemorySize, XPROJ_SMEM);
    cudaFuncSetAttribute(k_rnn,   cudaFuncAttributeMaxDynamicSharedMemorySize, RNN_SMEM);

    dim3 g1(HH / 64, TT / 64, BB);
    k_xproj<<<g1, 256, XPROJ_SMEM>>>(x, lengths, W_ih, b_ih);
    k_rnn<<<NCTA, 512, RNN_SMEM>>>(lengths, W_hh, b_hh, b_ih, W_out, b_out, out);
}